// round 13
// baseline (speedup 1.0000x reference)
#include <cuda_runtime.h>
#include <math.h>

// MT 1D forward + loss — q-form recursion + 4-way split + SKIN-DEPTH
// TRUNCATION + spectral load balancing.
//   Step (real scalar dropped, cancels in (S+D)/(S-D)):
//     T = E*D ; S' = S - q*T ; D' = q*S - T
//     E = exp(-arg)(cos arg - i sin arg), arg = s*T_j, s = sqrt(omega*mu)
//   Sensitivity of surface y to anything below layer J decays as
//   exp(-s*cumT[J]) -> keep only layers j <= C, C = min j: s*cumT[j] >= 16,
//   and start the chain with exact y = 1 ((S,D)=(1,0)) at the cut.
//   Mapping: each block takes one 32-freq chunk from each spectrum quarter
//   (lanes frequency-consecutive); roles rotated so each SMSP hosts 4 roles
//   x 4 different bands -> per-SMSP warp-steps ~155-190 instead of 255.
// Exact pow2 renorm every 8 steps per warp (cancels in the ratio).
// Loss reduction fused via fence + atomic ticket (reset for graph replay).

#define MU_F 1.2566370614359173e-6f
#define TWO_PI_F 6.283185307179586f
#define SQRT2_F 1.4142135623730951f
#define RAD2DEG_F 57.29577951308232f
#define NLOG2E_F (-1.4426950408889634f)
#define CUT_TH 16.0f

static __device__ float2 g_part[1024];
static __device__ unsigned g_ticket;   // zero-init; last block resets to 0

__device__ __forceinline__ void mk_e(float s, float4 L, float& ec, float& es)
{
    float arg = s * L.x;
    float e; asm("ex2.approx.ftz.f32 %0, %1;" : "=f"(e) : "f"(s * L.y));
    float sn, cs; __sincosf(arg, &sn, &cs);
    ec = e * cs; es = e * sn;          // E = ec - i*es
}

__device__ __forceinline__ void step_q(float q, float ec, float es,
    float& Sre, float& Sim, float& Dre, float& Dim)
{
    float Tre = ec * Dre + es * Dim;
    float Tim = ec * Dim - es * Dre;
    float nSre = Sre - q * Tre;
    float nSim = Sim - q * Tim;
    float nDre = q * Sre - Tre;
    float nDim = q * Sim - Tim;
    Sre = nSre; Sim = nSim; Dre = nDre; Dim = nDim;
}

__device__ __forceinline__ float pow2_scale(float m0)
{
    float m = fmaxf(m0, 1e-30f);
    unsigned eb = __float_as_uint(m) & 0x7f800000u;
    return __uint_as_float(0x7f000000u - eb);
}

__global__ __launch_bounds__(512, 1) void mt_fused(
    const float* __restrict__ rho, const float* __restrict__ thick,
    const float* __restrict__ freq, const float* __restrict__ obs_r,
    const float* __restrict__ obs_p, float* __restrict__ out,
    int nz, int nf, float invnf)
{
    // Layer record: x = sqrt2*t/sqrt(rho), y = -log2e*x, z = q
    __shared__ float4 sL[512];
    __shared__ float  cumT[512];         // inclusive prefix of sL[j].x
    __shared__ float4 sMat[3][128][4];   // [role-1][lslot]{m11,m21,m12,m22}
    __shared__ float s_y0, s_rho0;
    __shared__ int s_last;

    const int tid = threadIdx.x;
    const int nL = nz - 1;               // layers applied j = nL-1 .. 0
    for (int j = tid; j < nL; j += blockDim.x) {
        float r = rho[j];
        float T = SQRT2_F * thick[j] * rsqrtf(r);
        float w = (j > 0) ? sqrtf(r / rho[j - 1]) : 1.0f;
        float q = (w - 1.f) / (w + 1.f);
        sL[j] = make_float4(T, NLOG2E_F * T, q, 0.f);
    }
    if (tid == 0) {
        s_y0 = sqrtf(rho[nz - 1] / rho[nz - 2]);
        s_rho0 = rho[0];
    }
    __syncthreads();

    // cumT scan by warp 0 (blocked warp scan: 16 elems/lane covers 512)
    if (tid < 32) {
        float c[16]; float sum = 0.f;
        int base = tid * 16;
        #pragma unroll
        for (int k = 0; k < 16; ++k) {
            float v = (base + k < nL) ? sL[base + k].x : 0.f;
            sum += v; c[k] = sum;
        }
        float x = sum;
        #pragma unroll
        for (int o = 1; o < 32; o <<= 1) {
            float y = __shfl_up_sync(0xffffffffu, x, o);
            if (tid >= o) x += y;
        }
        float excl = x - sum;
        #pragma unroll
        for (int k = 0; k < 16; ++k) cumT[base + k] = c[k] + excl;
    }
    __syncthreads();

    const int lane = tid & 31;
    const int wr   = (tid >> 5) & 3;       // warp index within role
    const int role = tid >> 7;             // 0 = vector; 1..3 = matrix
    const int band = (wr + role) & 3;      // spectral quarter for this warp
    const int lslot = band * 32 + lane;    // logical freq slot within block

    const int qnf = nf >> 2;
    const bool strided = ((nf & 3) == 0) && (qnf == (int)gridDim.x * 32);
    int i = strided ? (band * qnf + (int)blockIdx.x * 32 + lane)
                    : ((int)blockIdx.x * 128 + lslot);
    const bool valid = (i < nf);
    if (i >= nf) i = nf - 1;               // clamp: uniform execution

    const float omu = TWO_PI_F * freq[i] * MU_F;
    const float s = sqrtf(omu);

    // cut index C: smallest j with s*cumT[j] >= CUT_TH (default nL-1)
    int C;
    {
        float th = CUT_TH / s;
        int lo = 0, hi = nL - 1;
        while (lo < hi) {
            int mid = (lo + hi) >> 1;
            if (cumT[mid] >= th) hi = mid; else lo = mid + 1;
        }
        C = lo;
    }

    const int nm = nL >> 2;                // per-matrix segment length

    float Sre, Sim, Dre, Dim;              // vector state (role 0)

    if (role == 0) {
        // ---- vector: layers j = min(nL-1, C) .. 3*nm ----
        bool nocut = (C >= nL - 1);
        float y0 = s_y0;
        Sre = nocut ? (y0 + 1.f) : 1.f;  Sim = 0.f;
        Dre = nocut ? (y0 - 1.f) : 0.f;  Dim = 0.f;
        int j = min(nL - 1, C);
        int cnt = j - 3 * nm + 1; if (cnt < 0) cnt = 0;
        int rem = cnt & 7;
        #pragma unroll 1
        for (int k = 0; k < rem; ++k, --j) {
            float4 L = sL[j]; float ec, es; mk_e(s, L, ec, es);
            step_q(L.z, ec, es, Sre, Sim, Dre, Dim);
        }
        cnt -= rem;
        while (cnt > 0) {
            #pragma unroll
            for (int k = 0; k < 8; ++k) {
                float4 L = sL[j - k]; float ec, es; mk_e(s, L, ec, es);
                step_q(L.z, ec, es, Sre, Sim, Dre, Dim);
            }
            j -= 8; cnt -= 8;
            float sc = pow2_scale(fmaxf(fmaxf(fabsf(Sre), fabsf(Sim)),
                                        fmaxf(fabsf(Dre), fabsf(Dim))));
            Sre *= sc; Sim *= sc; Dre *= sc; Dim *= sc;
        }
    } else {
        // ---- matrix role r: layers j = min(r*nm-1, C) .. (r-1)*nm ----
        float aSre = 1.f, aSim = 0.f, aDre = 0.f, aDim = 0.f;  // col1
        float bSre = 0.f, bSim = 0.f, bDre = 1.f, bDim = 0.f;  // col2
        int lo_r = (role - 1) * nm;
        int j = min(role * nm - 1, C);
        int cnt = j - lo_r + 1; if (cnt < 0) cnt = 0;
        int rem = cnt & 7;
        #pragma unroll 1
        for (int k = 0; k < rem; ++k, --j) {
            float4 L = sL[j]; float ec, es; mk_e(s, L, ec, es);
            step_q(L.z, ec, es, aSre, aSim, aDre, aDim);
            step_q(L.z, ec, es, bSre, bSim, bDre, bDim);
        }
        cnt -= rem;
        while (cnt > 0) {
            #pragma unroll
            for (int k = 0; k < 8; ++k) {
                float4 L = sL[j - k]; float ec, es; mk_e(s, L, ec, es);
                step_q(L.z, ec, es, aSre, aSim, aDre, aDim);
                step_q(L.z, ec, es, bSre, bSim, bDre, bDim);
            }
            j -= 8; cnt -= 8;
            float m1 = fmaxf(fmaxf(fabsf(aSre), fabsf(aSim)),
                             fmaxf(fabsf(aDre), fabsf(aDim)));
            float m2 = fmaxf(fmaxf(fabsf(bSre), fabsf(bSim)),
                             fmaxf(fabsf(bDre), fabsf(bDim)));
            float sc = pow2_scale(fmaxf(m1, m2));
            aSre *= sc; aSim *= sc; aDre *= sc; aDim *= sc;
            bSre *= sc; bSim *= sc; bDre *= sc; bDim *= sc;
        }
        sMat[role - 1][lslot][0] = make_float4(aSre, aSim, 0.f, 0.f);  // m11
        sMat[role - 1][lslot][1] = make_float4(aDre, aDim, 0.f, 0.f);  // m21
        sMat[role - 1][lslot][2] = make_float4(bSre, bSim, 0.f, 0.f);  // m12
        sMat[role - 1][lslot][3] = make_float4(bDre, bDim, 0.f, 0.f);  // m22
    }

    __syncthreads();                       // matrices published

    float t1 = 0.f, t2 = 0.f;
    if (role == 0) {
        // v = M1 * (M2 * (M3 * v))  (M3 deepest, applied first)
        #pragma unroll
        for (int r = 3; r >= 1; --r) {
            float4 m11 = sMat[r - 1][lslot][0];
            float4 m21 = sMat[r - 1][lslot][1];
            float4 m12 = sMat[r - 1][lslot][2];
            float4 m22 = sMat[r - 1][lslot][3];
            float nS_re = m11.x * Sre - m11.y * Sim + m12.x * Dre - m12.y * Dim;
            float nS_im = m11.x * Sim + m11.y * Sre + m12.x * Dim + m12.y * Dre;
            float nD_re = m21.x * Sre - m21.y * Sim + m22.x * Dre - m22.y * Dim;
            float nD_im = m21.x * Sim + m21.y * Sre + m22.x * Dim + m22.y * Dre;
            Sre = nS_re; Sim = nS_im; Dre = nD_re; Dim = nD_im;
        }

        // y = (S+D)/(S-D); Z = y*Z_L0, |Z_L0|^2 = omu*rho0, arg(Z_L0)=45deg
        float nre = Sre + Dre, nim = Sim + Dim;
        float dre = Sre - Dre, dim = Sim - Dim;
        float dd = dre * dre + dim * dim;
        float app_res = s_rho0 * (nre * nre + nim * nim) / dd;
        float yr = nre * dre + nim * dim;
        float yi = nim * dre - nre * dim;
        if (valid) {
            float dl = log10f(app_res) - log10f(obs_r[i]);
            t1 = dl * dl;
            float ph = atan2f(yi, yr) * RAD2DEG_F + 45.0f;
            float dp = ph - obs_p[i];
            t2 = dp * dp;
        }
    }

    // deterministic block reduction (16 warps)
    float x = t1, y = t2;
    #pragma unroll
    for (int o = 16; o > 0; o >>= 1) {
        x += __shfl_down_sync(0xffffffffu, x, o);
        y += __shfl_down_sync(0xffffffffu, y, o);
    }
    __shared__ float2 ws[16];
    int w = tid >> 5, l = tid & 31;
    if (l == 0) ws[w] = make_float2(x, y);
    __syncthreads();
    if (w == 0) {
        float2 vv = (l < 16) ? ws[l] : make_float2(0.f, 0.f);
        #pragma unroll
        for (int o = 8; o > 0; o >>= 1) {
            vv.x += __shfl_down_sync(0xffffffffu, vv.x, o);
            vv.y += __shfl_down_sync(0xffffffffu, vv.y, o);
        }
        if (l == 0) g_part[blockIdx.x] = vv;
    }

    // last-block final reduction (fence + ticket; reset keeps replays valid)
    __threadfence();
    if (tid == 0) {
        unsigned t = atomicAdd(&g_ticket, 1u);
        s_last = (t == gridDim.x - 1u);
    }
    __syncthreads();
    if (s_last) {
        int nb = gridDim.x;
        float fx = 0.f, fy = 0.f;
        for (int b = tid; b < nb; b += blockDim.x) {
            float2 p = g_part[b];
            fx += p.x; fy += p.y;
        }
        #pragma unroll
        for (int o = 16; o > 0; o >>= 1) {
            fx += __shfl_down_sync(0xffffffffu, fx, o);
            fy += __shfl_down_sync(0xffffffffu, fy, o);
        }
        __shared__ float2 ws2[16];
        if (l == 0) ws2[w] = make_float2(fx, fy);
        __syncthreads();
        if (tid == 0) {
            float gx = 0.f, gy = 0.f;
            int nw = (int)blockDim.x >> 5;
            for (int q = 0; q < nw; ++q) { gx += ws2[q].x; gy += ws2[q].y; }
            float lr = gx * invnf;
            float lp = gy * invnf;
            out[0] = lr + 10.f * lp;
            out[1] = lr;
            out[2] = lp;
            g_ticket = 0u;   // reset for next graph replay
        }
    }
}

extern "C" void kernel_launch(void* const* d_in, const int* in_sizes, int n_in,
                              void* d_out, int out_size)
{
    const float* rho    = (const float*)d_in[0];
    const float* thick  = (const float*)d_in[1];
    const float* freq   = (const float*)d_in[2];
    const float* obs_r  = (const float*)d_in[3];
    const float* obs_p  = (const float*)d_in[4];
    int nz = in_sizes[0];
    int nf = in_sizes[2];
    int blocks = (nf + 127) / 128;     // 128 freqs per block (512 threads)
    if (blocks > 1024) blocks = 1024;  // g_part capacity (nf=16384 -> 128)
    mt_fused<<<blocks, 512>>>(rho, thick, freq, obs_r, obs_p,
                              (float*)d_out, nz, nf, 1.f / (float)nf);
}